// round 1
// baseline (speedup 1.0000x reference)
#include <cuda_runtime.h>
#include <cuda_bf16.h>

// out[n, j] = x[n, j] + (1/512) * sum_{k=512..1023} x[n, k]
// x: [131072, 1024] f32, out: [131072, 512] f32
//
// One block (128 threads) per row.
//   - tail reduce: each thread loads one float4 from x[row, 512 + 4*tid]
//   - warp shfl reduce -> 4 partials -> smem -> warp0 reduce -> broadcast
//   - head: each thread loads one float4 from x[row, 4*tid], adds s, stores.
// All global accesses are 16B, fully coalesced (128 thr * 16B = 2KB lines).

static constexpr int ROW_IN   = 1024;
static constexpr int ROW_OUT  = 512;
static constexpr int THREADS  = 128;

__global__ __launch_bounds__(THREADS)
void projection_kernel(const float* __restrict__ x,
                       float* __restrict__ out,
                       int n_rows)
{
    int row = blockIdx.x;
    if (row >= n_rows) return;

    const float4* xrow  = reinterpret_cast<const float4*>(x + (size_t)row * ROW_IN);
    float4*       orow  = reinterpret_cast<float4*>(out + (size_t)row * ROW_OUT);

    int tid  = threadIdx.x;
    int lane = tid & 31;
    int warp = tid >> 5;

    // ---- Issue BOTH loads up front (MLP: 2 outstanding float4 per thread) ----
    // tail: elements [512, 1024) -> float4 index [128, 256)
    float4 t = xrow[128 + tid];
    // head: elements [0, 512) -> float4 index [0, 128)
    float4 h = xrow[tid];

    float s = t.x + t.y + t.z + t.w;

    // warp reduce
    #pragma unroll
    for (int off = 16; off > 0; off >>= 1)
        s += __shfl_xor_sync(0xFFFFFFFFu, s, off);

    __shared__ float partial[4];
    if (lane == 0) partial[warp] = s;
    __syncthreads();

    // every thread computes the final sum from the 4 partials (cheap, no 2nd sync)
    float total = partial[0] + partial[1] + partial[2] + partial[3];
    float mean = total * (1.0f / 512.0f);

    h.x += mean; h.y += mean; h.z += mean; h.w += mean;
    orow[tid] = h;
}

extern "C" void kernel_launch(void* const* d_in, const int* in_sizes, int n_in,
                              void* d_out, int out_size)
{
    const float* x = (const float*)d_in[0];
    float* out = (float*)d_out;

    int n_rows = in_sizes[0] / ROW_IN;   // 131072

    projection_kernel<<<n_rows, THREADS>>>(x, out, n_rows);
}